// round 6
// baseline (speedup 1.0000x reference)
#include <cuda_runtime.h>

#define Bv 8
#define Tv 1000
#define Dv 1024
#define NCHUNK 125   // 125 chunks x 8 rows = 1000, uniform; grid 1000 blocks

// Scratch (__device__ globals per allocation rules)
__device__ float g_part[NCHUNK * 8 * 1024];  // per-chunk partial t-sums
__device__ float g_vsump[4 * 8 * 64];        // 4 j-block partials of vsum

// ---------------------------------------------------------------------------
// 1) Partial sums over t: 125 chunks of exactly 8 rows. grid (125, 8),
//    256 threads, one float4 column-slice per thread, fully unrolled (MLP=8).
// ---------------------------------------------------------------------------
__global__ void __launch_bounds__(256)
xsum_part_kernel(const float* __restrict__ x)
{
    const int chunk = blockIdx.x;        // 0..124
    const int b     = blockIdx.y;        // 0..7
    const int j4    = threadIdx.x << 2;

    const float4* xp = (const float4*)(x + ((size_t)b * Tv + chunk * 8) * Dv + j4);
    float4 v0 = xp[0 * 256], v1 = xp[1 * 256], v2 = xp[2 * 256], v3 = xp[3 * 256];
    float4 v4 = xp[4 * 256], v5 = xp[5 * 256], v6 = xp[6 * 256], v7 = xp[7 * 256];

    float4 acc;
    acc.x = (v0.x + v1.x) + (v2.x + v3.x) + ((v4.x + v5.x) + (v6.x + v7.x));
    acc.y = (v0.y + v1.y) + (v2.y + v3.y) + ((v4.y + v5.y) + (v6.y + v7.y));
    acc.z = (v0.z + v1.z) + (v2.z + v3.z) + ((v4.z + v5.z) + (v6.z + v7.z));
    acc.w = (v0.w + v1.w) + (v2.w + v3.w) + ((v4.w + v5.w) + (v6.w + v7.w));

    *(float4*)(g_part + ((size_t)(chunk * 8 + b)) * Dv + j4) = acc;
}

// ---------------------------------------------------------------------------
// 2) vsum partials: grid (8 b, 4 jblk). Reduce the 125 chunk-partials over
//    this 256-wide j slice, then GEMV vs Wv -> g_vsump[jblk][b][64].
// ---------------------------------------------------------------------------
__global__ void __launch_bounds__(256)
vsum_part_kernel(const float* __restrict__ Wv)
{
    __shared__ float xs[256];
    __shared__ float p[4][64];
    const int b    = blockIdx.x;
    const int jblk = blockIdx.y;
    const int tid  = threadIdx.x;
    const int jg   = jblk * 256;

    {
        float s = 0.f;
        #pragma unroll 25
        for (int c = 0; c < NCHUNK; c++)
            s += g_part[((size_t)(c * 8 + b)) * Dv + jg + tid];
        xs[tid] = s;
    }
    __syncthreads();

    const int d   = tid & 63;
    const int sub = tid >> 6;
    float acc = 0.f;
    #pragma unroll 16
    for (int jj = 0; jj < 64; jj++) {
        int j = sub * 64 + jj;
        acc += xs[j] * Wv[(size_t)(jg + j) * 64 + d];
    }
    p[sub][d] = acc;
    __syncthreads();
    if (tid < 64)
        g_vsump[(jblk * 8 + b) * 64 + tid] =
            p[0][tid] + p[1][tid] + p[2][tid] + p[3][tid];
}

// ---------------------------------------------------------------------------
// 3) Fused row-GEMV + broadcast write. grid (32 n-blocks, 8 t-chunks), 256 thr.
//    row[b,n] = bo[n] + sum_m vs[b, m&63] * Wo[m, n]; the two 64-aligned halves
//    per warp share d = m&63 (fold w1+w2). Then stream 125 t x 8 b rows.
// ---------------------------------------------------------------------------
__global__ void __launch_bounds__(256)
row_bcast_kernel(const float* __restrict__ Wo, const float* __restrict__ bv,
                 const float* __restrict__ bo, float* __restrict__ out)
{
    __shared__ float vs[8 * 64];      // vsum[b][d]
    __shared__ float part[8][8][32];  // [warp][b][lane]
    __shared__ float fin[8][32];      // final row slice [b][lane]

    const int n0   = blockIdx.x * 32;
    const int t0   = blockIdx.y * 125;
    const int tid  = threadIdx.x;
    const int lane = tid & 31;
    const int wid  = tid >> 5;
    const int n    = n0 + lane;

    // Assemble vsum: 4 j-block partials + T*bv
    #pragma unroll
    for (int i = tid; i < 512; i += 256) {
        int d = i & 63;
        float s = (float)Tv * bv[d];
        #pragma unroll
        for (int jb = 0; jb < 4; jb++)
            s += g_vsump[jb * 512 + i];
        vs[i] = s;
    }
    __syncthreads();

    // GEMV over this warp's 128 m-rows (two h-halves folded)
    float acc[8] = {};
    const int mbase = wid * 128;
    #pragma unroll 8
    for (int mm = 0; mm < 64; mm++) {
        float w1 = Wo[(size_t)(mbase + mm) * Dv + n];
        float w2 = Wo[(size_t)(mbase + mm + 64) * Dv + n];
        float w  = w1 + w2;
        #pragma unroll
        for (int b = 0; b < 8; b++)
            acc[b] = fmaf(vs[b * 64 + mm], w, acc[b]);
    }
    #pragma unroll
    for (int b = 0; b < 8; b++)
        part[wid][b][lane] = acc[b];
    __syncthreads();

    // Cross-warp reduce + bias
    {
        int b = wid;
        float s = bo[n];
        #pragma unroll
        for (int w = 0; w < 8; w++)
            s += part[w][b][lane];
        fin[b][lane] = s;
    }
    __syncthreads();

    // Broadcast write: warp w owns batch w; 125 t-rows of 32 floats (128B coalesced)
    {
        const int b = wid;
        const float v = fin[b][lane];
        float* op = out + ((size_t)(b * Tv + t0)) * Dv + n;
        #pragma unroll 5
        for (int t = 0; t < 125; t++)
            op[(size_t)t * Dv] = v;
    }
}

// ---------------------------------------------------------------------------
extern "C" void kernel_launch(void* const* d_in, const int* in_sizes, int n_in,
                              void* d_out, int out_size)
{
    const float* x  = (const float*)d_in[0];
    const float* Wv = (const float*)d_in[5];
    const float* bv = (const float*)d_in[6];
    const float* Wo = (const float*)d_in[7];
    const float* bo = (const float*)d_in[8];
    float* out = (float*)d_out;

    xsum_part_kernel<<<dim3(NCHUNK, 8), 256>>>(x);
    vsum_part_kernel<<<dim3(8, 4), 256>>>(Wv);
    row_bcast_kernel<<<dim3(32, 8), 256>>>(Wo, bv, bo, out);
}

// round 7
// speedup vs baseline: 1.1472x; 1.1472x over previous
#include <cuda_runtime.h>

#define Bv 8
#define Tv 1000
#define Dv 1024
#define NCHUNK 125   // 125 chunks x 8 rows = 1000

// Scratch (__device__ globals per allocation rules)
__device__ float g_part[NCHUNK * 8 * 1024];  // per-chunk partial t-sums
__device__ float g_vsump[16 * 8 * 64];       // 16 j-slice partials of vsum
__device__ float g_row[8 * 1024];            // per-batch output row

// ---------------------------------------------------------------------------
// 1) Partial sums over t: grid (125, 8), 256 threads, 8 batched LDG.128.
// ---------------------------------------------------------------------------
__global__ void __launch_bounds__(256)
xsum_part_kernel(const float* __restrict__ x)
{
    const int chunk = blockIdx.x;
    const int b     = blockIdx.y;
    const int j4    = threadIdx.x << 2;

    const float4* xp = (const float4*)(x + ((size_t)b * Tv + chunk * 8) * Dv + j4);
    float4 v0 = xp[0 * 256], v1 = xp[1 * 256], v2 = xp[2 * 256], v3 = xp[3 * 256];
    float4 v4 = xp[4 * 256], v5 = xp[5 * 256], v6 = xp[6 * 256], v7 = xp[7 * 256];

    float4 acc;
    acc.x = ((v0.x + v1.x) + (v2.x + v3.x)) + ((v4.x + v5.x) + (v6.x + v7.x));
    acc.y = ((v0.y + v1.y) + (v2.y + v3.y)) + ((v4.y + v5.y) + (v6.y + v7.y));
    acc.z = ((v0.z + v1.z) + (v2.z + v3.z)) + ((v4.z + v5.z) + (v6.z + v7.z));
    acc.w = ((v0.w + v1.w) + (v2.w + v3.w)) + ((v4.w + v5.w) + (v6.w + v7.w));

    *(float4*)(g_part + ((size_t)(chunk * 8 + b)) * Dv + j4) = acc;
}

// ---------------------------------------------------------------------------
// 2) vsum partials: grid (8 b, 16 jb). Each block owns a 64-wide j slice.
//    256 thr = 4 chunk-segments x 64 j. Reduce 125 chunk-partials, then
//    GEMV the 64-j slice against Wv -> g_vsump[(jb*8+b)][64].
// ---------------------------------------------------------------------------
__global__ void __launch_bounds__(256)
vsum_part_kernel(const float* __restrict__ Wv)
{
    __shared__ float xr[4][64];   // chunk-segment partials
    __shared__ float xs[64];      // reduced x-sums for this j slice
    __shared__ float p[4][64];    // GEMV j-segment partials
    const int b   = blockIdx.x;
    const int jb  = blockIdx.y;
    const int tid = threadIdx.x;
    const int j   = tid & 63;     // j within slice
    const int seg = tid >> 6;     // 0..3
    const int jg  = jb * 64;

    // Phase 1: reduce chunks. Segments 0-2 take 31 chunks, segment 3 takes 32.
    {
        const int c0 = seg * 31;
        const int cn = (seg == 3) ? 32 : 31;
        float s = 0.f;
        #pragma unroll 31
        for (int c = 0; c < cn; c++)
            s += g_part[((size_t)((c0 + c) * 8 + b)) * Dv + jg + j];
        xr[seg][j] = s;
    }
    __syncthreads();
    if (seg == 0)
        xs[j] = xr[0][j] + xr[1][j] + xr[2][j] + xr[3][j];
    __syncthreads();

    // Phase 2: GEMV 64 j x 64 d; each segment handles 16 j's.
    {
        const int d = j;          // reuse lanes: d = tid & 63
        float acc = 0.f;
        #pragma unroll
        for (int jj = 0; jj < 16; jj++) {
            int jl = seg * 16 + jj;
            acc += xs[jl] * Wv[(size_t)(jg + jl) * 64 + d];
        }
        p[seg][d] = acc;
    }
    __syncthreads();
    if (seg == 0)
        g_vsump[(jb * 8 + b) * 64 + j] = p[0][j] + p[1][j] + p[2][j] + p[3][j];
}

// ---------------------------------------------------------------------------
// 3) row[b,n] = bo[n] + sum_m vs[b, m&63] * Wo[m,n]. grid 32 (32 cols each),
//    256 thr; warp w covers m in [w*128, w*128+128), two 64-halves folded.
// ---------------------------------------------------------------------------
__global__ void __launch_bounds__(256)
row_kernel(const float* __restrict__ Wo, const float* __restrict__ bv,
           const float* __restrict__ bo)
{
    __shared__ float vs[8 * 64];
    __shared__ float part[8][8][32];

    const int n0   = blockIdx.x * 32;
    const int tid  = threadIdx.x;
    const int lane = tid & 31;
    const int wid  = tid >> 5;
    const int n    = n0 + lane;

    // Assemble vsum: 16 j-slice partials + T*bv. 512 outputs, 2 per thread.
    #pragma unroll
    for (int i = tid; i < 512; i += 256) {
        int d = i & 63;
        float s = (float)Tv * bv[d];
        #pragma unroll
        for (int jb = 0; jb < 16; jb++)
            s += g_vsump[jb * 512 + i];
        vs[i] = s;
    }
    __syncthreads();

    float acc[8] = {};
    const int mbase = wid * 128;
    #pragma unroll 8
    for (int mm = 0; mm < 64; mm++) {
        float w1 = Wo[(size_t)(mbase + mm) * Dv + n];
        float w2 = Wo[(size_t)(mbase + mm + 64) * Dv + n];
        float w  = w1 + w2;
        #pragma unroll
        for (int b = 0; b < 8; b++)
            acc[b] = fmaf(vs[b * 64 + mm], w, acc[b]);
    }
    #pragma unroll
    for (int b = 0; b < 8; b++)
        part[wid][b][lane] = acc[b];
    __syncthreads();

    {
        int b = wid;
        float s = bo[n];
        #pragma unroll
        for (int w = 0; w < 8; w++)
            s += part[w][b][lane];
        g_row[b * Dv + n] = s;
    }
}

// ---------------------------------------------------------------------------
// 4) Broadcast: grid (125, 8), 256 threads. One float4/thread from g_row,
//    8 fully-unrolled STG.128 rows.
// ---------------------------------------------------------------------------
__global__ void __launch_bounds__(256)
bcast_kernel(float* __restrict__ out)
{
    const int chunk = blockIdx.x;
    const int b     = blockIdx.y;

    float4 v = ((const float4*)g_row)[b * 256 + threadIdx.x];
    float4* op = (float4*)out + ((size_t)b * Tv + chunk * 8) * 256 + threadIdx.x;
    op[0 * 256] = v;  op[1 * 256] = v;  op[2 * 256] = v;  op[3 * 256] = v;
    op[4 * 256] = v;  op[5 * 256] = v;  op[6 * 256] = v;  op[7 * 256] = v;
}

// ---------------------------------------------------------------------------
extern "C" void kernel_launch(void* const* d_in, const int* in_sizes, int n_in,
                              void* d_out, int out_size)
{
    const float* x  = (const float*)d_in[0];
    const float* Wv = (const float*)d_in[5];
    const float* bv = (const float*)d_in[6];
    const float* Wo = (const float*)d_in[7];
    const float* bo = (const float*)d_in[8];
    float* out = (float*)d_out;

    xsum_part_kernel<<<dim3(NCHUNK, 8), 256>>>(x);
    vsum_part_kernel<<<dim3(8, 16), 256>>>(Wv);
    row_kernel<<<32, 256>>>(Wo, bv, bo);
    bcast_kernel<<<dim3(NCHUNK, 8), 256>>>(out);
}